// round 3
// baseline (speedup 1.0000x reference)
#include <cuda_runtime.h>
#include <cuda_bf16.h>

// Shapes (fixed by the problem): B=8, N=2048, low=512, high=4096
#define Bb 8
#define Nn 2048
#define LO 512
#define HI 4096
#define BIGF 9.0e15f

// ---------------- scratch (device globals; no allocation allowed) ----------
__device__ float g_G[Bb * LO * LO];    // X^T X per batch
__device__ float g_T[Bb * LO * LO];    // Wq * G
__device__ float g_E[Bb * LO * HI];    // e raw, overwritten in-place with attn A
__device__ float g_P[Bb * LO * HI];    // Wv^T * A
__device__ float g_R[Bb * LO * HI];    // P * O^T
__device__ float g_s[Bb * LO];         // colsum of X
__device__ float g_u[Bb * LO];         // Wq * s
__device__ float g_v[Bb * HI];         // Wk * s
__device__ float g_w[Bb * HI];         // bv^T * A
__device__ float g_z[Bb * HI];         // (bv^T A) O^T + o_b  (per-batch output bias)

// ---------------- generic tiled SGEMM --------------------------------------
// C[M,N] = op(A) * op(B) (+ bias row), batched over blockIdx.z.
// TA: a(m,k) = A[k*lda + m]   else A[m*lda + k]
// TB: b(k,n) = B[n*ldb + k]   else B[k*ldb + n]
// All M,N multiples of 128 and K multiples of 16 here -> no bounds checks.
template <bool TA, bool TB, bool BIAS>
__global__ void __launch_bounds__(256) gemm_kernel(
    int M, int N, int K,
    const float* __restrict__ A, int lda, long sA,
    const float* __restrict__ B, int ldb, long sB,
    float* __restrict__ C, int ldc, long sC,
    const float* __restrict__ bias, long sBias)
{
    __shared__ __align__(16) float As[16][132];
    __shared__ __align__(16) float Bs[16][132];

    const int bz = blockIdx.z;
    A += (long)bz * sA;
    B += (long)bz * sB;
    C += (long)bz * sC;

    const int tid  = threadIdx.x;
    const int row0 = blockIdx.y * 128;
    const int col0 = blockIdx.x * 128;
    const int tm   = (tid >> 4) * 8;   // 16 thread-rows
    const int tn   = (tid & 15) * 8;   // 16 thread-cols

    float acc[8][8];
#pragma unroll
    for (int i = 0; i < 8; i++)
#pragma unroll
        for (int j = 0; j < 8; j++) acc[i][j] = 0.f;

    for (int k0 = 0; k0 < K; k0 += 16) {
        if (TA) {
#pragma unroll
            for (int i = 0; i < 8; i++) {
                int idx = tid + i * 256;
                int k = idx >> 7, m = idx & 127;
                As[k][m] = A[(long)(k0 + k) * lda + row0 + m];
            }
        } else {
#pragma unroll
            for (int i = 0; i < 8; i++) {
                int idx = tid + i * 256;
                int m = idx >> 4, k = idx & 15;
                As[k][m] = A[(long)(row0 + m) * lda + k0 + k];
            }
        }
        if (TB) {
#pragma unroll
            for (int i = 0; i < 8; i++) {
                int idx = tid + i * 256;
                int n = idx >> 4, k = idx & 15;
                Bs[k][n] = B[(long)(col0 + n) * ldb + k0 + k];
            }
        } else {
#pragma unroll
            for (int i = 0; i < 8; i++) {
                int idx = tid + i * 256;
                int k = idx >> 7, n = idx & 127;
                Bs[k][n] = B[(long)(k0 + k) * ldb + col0 + n];
            }
        }
        __syncthreads();

#pragma unroll
        for (int k = 0; k < 16; k++) {
            float4 a0 = *(const float4*)&As[k][tm];
            float4 a1 = *(const float4*)&As[k][tm + 4];
            float4 b0 = *(const float4*)&Bs[k][tn];
            float4 b1 = *(const float4*)&Bs[k][tn + 4];
            float a[8] = {a0.x, a0.y, a0.z, a0.w, a1.x, a1.y, a1.z, a1.w};
            float bb[8] = {b0.x, b0.y, b0.z, b0.w, b1.x, b1.y, b1.z, b1.w};
#pragma unroll
            for (int i = 0; i < 8; i++)
#pragma unroll
                for (int j = 0; j < 8; j++) acc[i][j] += a[i] * bb[j];
        }
        __syncthreads();
    }

    float bvv[8];
    if (BIAS) {
#pragma unroll
        for (int j = 0; j < 8; j++) bvv[j] = bias[(long)bz * sBias + col0 + tn + j];
    }
#pragma unroll
    for (int i = 0; i < 8; i++) {
        float* crow = C + (long)(row0 + tm + i) * ldc + col0 + tn;
#pragma unroll
        for (int j = 0; j < 8; j++) {
            float v = acc[i][j];
            if (BIAS) v += bvv[j];
            crow[j] = v;
        }
    }
}

// ---------------- small helper kernels --------------------------------------
__device__ __forceinline__ float warpSum(float v) {
#pragma unroll
    for (int o = 16; o; o >>= 1) v += __shfl_xor_sync(0xffffffffu, v, o);
    return v;
}

// colsum: s[b][m] = sum_n X[b,n,m]
__global__ void colsum_kernel(const float* __restrict__ X, float* __restrict__ s) {
    int b = blockIdx.x, m = threadIdx.x;  // 512 threads
    const float* xb = X + (long)b * Nn * LO;
    float acc = 0.f;
    for (int n = 0; n < Nn; n++) acc += xb[(long)n * LO + m];
    s[b * LO + m] = acc;
}

// rowdot: out[b][r] = sum_c W[r,c]*x[b,c] (+ addv[r])  — one warp per row
__global__ void rowdot_kernel(const float* __restrict__ W, const float* __restrict__ x,
                              float* __restrict__ out, int rows, int cols,
                              const float* __restrict__ addv) {
    int warp = threadIdx.x >> 5, lane = threadIdx.x & 31;
    int r = blockIdx.x * 8 + warp;
    int b = blockIdx.y;
    if (r >= rows) return;
    const float* xb = x + (long)b * cols;
    const float* wr = W + (long)r * cols;
    float s = 0.f;
    for (int c = lane; c < cols; c += 32) s += wr[c] * xb[c];
    s = warpSum(s);
    if (lane == 0) out[(long)b * rows + r] = s + (addv ? addv[r] : 0.f);
}

// wvec: w[b][h] = sum_l bv[l] * A[b,l,h]
__global__ void wvec_kernel(const float* __restrict__ Amat, const float* __restrict__ bv,
                            float* __restrict__ w) {
    int h = blockIdx.x * 256 + threadIdx.x;
    int b = blockIdx.y;
    const float* Ab = Amat + (long)b * LO * HI;
    float acc = 0.f;
    for (int l = 0; l < LO; l++) acc += bv[l] * Ab[(long)l * HI + h];
    w[(long)b * HI + h] = acc;
}

// ---------------- fused softmax + min-max-norm attention combine ------------
// In-place on g_E: reads raw e' = Wq G Wk^T, applies bias terms and 1/64 scale,
// writes A = softmax_global(e) + softmax_local(minmaxnorm(e, mask)).
__global__ void __launch_bounds__(256) attn_kernel(
    float* __restrict__ E, const int* __restrict__ linkage,
    const float* __restrict__ u, const float* __restrict__ bq,
    const float* __restrict__ v, const float* __restrict__ bk)
{
    __shared__ float red[8];
    const int l = blockIdx.x, b = blockIdx.y;
    float* row = E + ((long)(b * LO + l)) * HI;
    const int* lrow = linkage + (long)l * HI;
    const float* vb = v + (long)b * HI;
    const float uval = u[b * LO + l];
    const float bqv  = bq[l];

    float ev[16];
    unsigned mbits = 0;
    float gmax = -3.4e38f, mn = BIGF, mx = -BIGF;

#pragma unroll
    for (int j = 0; j < 16; j++) {
        int h = threadIdx.x + j * 256;
        float bkh = bk[h];
        float e = (row[h] + uval * bkh + bqv * (vb[h] + (float)Nn * bkh)) * 0.015625f;
        ev[j] = e;
        gmax = fmaxf(gmax, e);
        if (lrow[h] > 0) {
            mbits |= 1u << j;
            mn = fminf(mn, e);
            mx = fmaxf(mx, e);
        }
    }

    // --- block reductions (max / min / max) ---
    const int wid = threadIdx.x >> 5, lane = threadIdx.x & 31;
#pragma unroll
    for (int o = 16; o; o >>= 1) gmax = fmaxf(gmax, __shfl_xor_sync(0xffffffffu, gmax, o));
    if (lane == 0) red[wid] = gmax;
    __syncthreads();
    gmax = red[0];
#pragma unroll
    for (int i = 1; i < 8; i++) gmax = fmaxf(gmax, red[i]);
    __syncthreads();

#pragma unroll
    for (int o = 16; o; o >>= 1) mn = fminf(mn, __shfl_xor_sync(0xffffffffu, mn, o));
    if (lane == 0) red[wid] = mn;
    __syncthreads();
    mn = red[0];
#pragma unroll
    for (int i = 1; i < 8; i++) mn = fminf(mn, red[i]);
    __syncthreads();

#pragma unroll
    for (int o = 16; o; o >>= 1) mx = fmaxf(mx, __shfl_xor_sync(0xffffffffu, mx, o));
    if (lane == 0) red[wid] = mx;
    __syncthreads();
    mx = red[0];
#pragma unroll
    for (int i = 1; i < 8; i++) mx = fmaxf(mx, red[i]);
    __syncthreads();

    float den = mx - mn;
    if (den == 0.0f) den = 1e-6f;
    const bool hasMask = (mx != -BIGF);
    // local softmax max: max over mask of (e-mn)/den is exactly (mx-mn)/den;
    // with no mask every value is -BIG.
    const float lmax = hasMask ? (((mx - mn) == 0.0f) ? 0.0f : 1.0f) : -BIGF;

    float eg[16], el[16];
    float gsum = 0.f, lsum = 0.f;
#pragma unroll
    for (int j = 0; j < 16; j++) {
        float e = ev[j];
        float g = __expf(e - gmax);
        eg[j] = g;
        gsum += g;
        float lv = ((mbits >> j) & 1) ? (e - mn) / den : -BIGF;
        float ll = __expf(lv - lmax);
        el[j] = ll;
        lsum += ll;
    }

    gsum = warpSum(gsum);
    if (lane == 0) red[wid] = gsum;
    __syncthreads();
    gsum = red[0];
#pragma unroll
    for (int i = 1; i < 8; i++) gsum += red[i];
    __syncthreads();

    lsum = warpSum(lsum);
    if (lane == 0) red[wid] = lsum;
    __syncthreads();
    lsum = red[0];
#pragma unroll
    for (int i = 1; i < 8; i++) lsum += red[i];

    const float rg = 1.0f / gsum, rl = 1.0f / lsum;
#pragma unroll
    for (int j = 0; j < 16; j++) {
        int h = threadIdx.x + j * 256;
        row[h] = eg[j] * rg + el[j] * rl;
    }
}

// ---------------- host launch ------------------------------------------------
static float* symaddr(const void* sym) {
    void* p = nullptr;
    cudaGetSymbolAddress(&p, sym);
    return (float*)p;
}

extern "C" void kernel_launch(void* const* d_in, const int* in_sizes, int n_in,
                              void* d_out, int out_size) {
    const float* X   = (const float*)d_in[0];
    const int*   lk  = (const int*)d_in[1];
    const float* wq  = (const float*)d_in[2];
    const float* bq  = (const float*)d_in[3];
    const float* wk  = (const float*)d_in[4];
    const float* bk  = (const float*)d_in[5];
    const float* wv  = (const float*)d_in[6];
    const float* bv  = (const float*)d_in[7];
    const float* ow  = (const float*)d_in[8];
    const float* ob  = (const float*)d_in[9];
    float* out = (float*)d_out;

    float* G = symaddr(g_G);
    float* T = symaddr(g_T);
    float* E = symaddr(g_E);
    float* P = symaddr(g_P);
    float* R = symaddr(g_R);
    float* s = symaddr(g_s);
    float* u = symaddr(g_u);
    float* v = symaddr(g_v);
    float* w = symaddr(g_w);
    float* z = symaddr(g_z);

    // bias correction vectors (all-zero in this dataset, but exact in general)
    colsum_kernel<<<Bb, LO>>>(X, s);
    rowdot_kernel<<<dim3(LO / 8, Bb), 256>>>(wq, s, u, LO, LO, nullptr);
    rowdot_kernel<<<dim3(HI / 8, Bb), 256>>>(wk, s, v, HI, LO, nullptr);

    // G_b = X_b^T X_b              [512,512]   (TN)
    gemm_kernel<true, false, false><<<dim3(LO / 128, LO / 128, Bb), 256>>>(
        LO, LO, Nn, X, LO, (long)Nn * LO, X, LO, (long)Nn * LO,
        G, LO, (long)LO * LO, nullptr, 0);

    // T_b = Wq * G_b               [512,512]   (NN)
    gemm_kernel<false, false, false><<<dim3(LO / 128, LO / 128, Bb), 256>>>(
        LO, LO, LO, wq, LO, 0, G, LO, (long)LO * LO,
        T, LO, (long)LO * LO, nullptr, 0);

    // E_b = T_b * Wk^T (raw)       [512,4096]  (NT)
    gemm_kernel<false, true, false><<<dim3(HI / 128, LO / 128, Bb), 256>>>(
        LO, HI, LO, T, LO, (long)LO * LO, wk, LO, 0,
        E, HI, (long)LO * HI, nullptr, 0);

    // A_b = softmax(e) + softmax(minmaxnorm(e, mask)), in place in E
    attn_kernel<<<dim3(LO, Bb), 256>>>(E, lk, u, bq, v, bk);

    // bias path: w_b = bv^T A_b ; z_b = w_b O^T + o_b
    wvec_kernel<<<dim3(HI / 256, Bb), 256>>>(E, bv, w);
    rowdot_kernel<<<dim3(HI / 8, Bb), 256>>>(ow, w, z, HI, HI, ob);

    // P_b = Wv^T * A_b             [512,4096]  (TN)
    gemm_kernel<true, false, false><<<dim3(HI / 128, LO / 128, Bb), 256>>>(
        LO, HI, LO, wv, LO, 0, E, HI, (long)LO * HI,
        P, HI, (long)LO * HI, nullptr, 0);

    // R_b = P_b * O^T              [512,4096]  (NT)  -- dominant GEMM, K=4096
    gemm_kernel<false, true, false><<<dim3(HI / 128, LO / 128, Bb), 256>>>(
        LO, HI, HI, P, HI, (long)LO * HI, ow, HI, 0,
        R, HI, (long)LO * HI, nullptr, 0);

    // out_b = X_b * R_b + z_b      [2048,4096] (NN + bias row)
    gemm_kernel<false, false, true><<<dim3(HI / 128, Nn / 128, Bb), 256>>>(
        Nn, HI, LO, X, LO, (long)Nn * LO, R, HI, (long)LO * HI,
        out, HI, (long)Nn * HI, z, HI);

    (void)in_sizes; (void)n_in; (void)out_size;
}

// round 6
// speedup vs baseline: 2.7473x; 2.7473x over previous
#include <cuda_runtime.h>
#include <cuda_bf16.h>
#include <cstdint>

// Shapes (fixed by the problem): B=8, N=2048, low=512, high=4096
#define Bb 8
#define Nn 2048
#define LO 512
#define HI 4096
#define BIGF 9.0e15f

// tripled-K sizes for bf16x3 split GEMMs
#define K1 (3*Nn)   // 6144  (G = Xt Xt^T)
#define K2 (3*LO)   // 1536
#define K5 (3*HI)   // 12288 (R = P O^T)

// ---------------- fp32 scratch --------------------------------------------
__device__ float g_G[Bb*LO*LO];
__device__ float g_T[Bb*LO*LO];
__device__ float g_E[Bb*LO*HI];
__device__ float g_P[Bb*LO*HI];
__device__ float g_R[Bb*LO*HI];
__device__ float g_s[Bb*LO];
__device__ float g_u[Bb*LO];
__device__ float g_v[Bb*HI];
__device__ float g_w[Bb*HI];
__device__ float g_z[Bb*HI];

// ---------------- bf16 split operands (K-major) ---------------------------
__device__ __align__(256) __nv_bfloat16 g_XtA[Bb*LO*K1];
__device__ __align__(256) __nv_bfloat16 g_XtB[Bb*LO*K1];
__device__ __align__(256) __nv_bfloat16 g_WqA[LO*K2];
__device__ __align__(256) __nv_bfloat16 g_GB [Bb*LO*K2];
__device__ __align__(256) __nv_bfloat16 g_TA [Bb*LO*K2];
__device__ __align__(256) __nv_bfloat16 g_WkB[HI*K2];
__device__ __align__(256) __nv_bfloat16 g_WvTA[LO*K2];
__device__ __align__(256) __nv_bfloat16 g_AtB[Bb*HI*K2];
__device__ __align__(256) __nv_bfloat16 g_PA [Bb*LO*K5];
__device__ __align__(256) __nv_bfloat16 g_OB [HI*K5];
__device__ __align__(256) __nv_bfloat16 g_RtB[Bb*HI*K2];
__device__ __align__(256) __nv_bfloat16 g_XA [Bb*Nn*K2];

// ---------------- PTX helpers ----------------------------------------------
__device__ __forceinline__ uint32_t s2u(const void* p) {
    uint32_t a;
    asm("{ .reg .u64 t; cvta.to.shared.u64 t, %1; cvt.u32.u64 %0, t; }" : "=r"(a) : "l"(p));
    return a;
}
#define SWZ(x) ((x) ^ (((x) >> 3) & 0x70))

__device__ __forceinline__ void cp16(uint32_t sa, const void* ga) {
    asm volatile("cp.async.cg.shared.global [%0], [%1], 16;" :: "r"(sa), "l"(ga));
}

__device__ __forceinline__ void ldsm4(uint32_t& r0, uint32_t& r1, uint32_t& r2,
                                      uint32_t& r3, uint32_t a) {
    asm volatile("ldmatrix.sync.aligned.m8n8.x4.shared.b16 {%0,%1,%2,%3}, [%4];"
        : "=r"(r0), "=r"(r1), "=r"(r2), "=r"(r3) : "r"(a));
}

__device__ __forceinline__ void mma16816(float* d, const uint32_t* a,
                                         uint32_t b0, uint32_t b1) {
    asm volatile(
        "mma.sync.aligned.m16n8k16.row.col.f32.bf16.bf16.f32 "
        "{%0,%1,%2,%3}, {%4,%5,%6,%7}, {%8,%9}, {%0,%1,%2,%3};"
        : "+f"(d[0]), "+f"(d[1]), "+f"(d[2]), "+f"(d[3])
        : "r"(a[0]), "r"(a[1]), "r"(a[2]), "r"(a[3]), "r"(b0), "r"(b1));
}

// ---------------- HMMA GEMM: C[M,N] = A[M,K]·B[N,K]^T (bf16 in, fp32 out) --
// CTA tile 128x128, 8 warps (warp tile 32x64), K-chunk 64, 3-stage cp.async.
#define STAGES 3
#define KCH 64
#define STAGE_A 16384                // 128 rows x 128 B
#define STAGE_BYTES 32768            // A (16KB) + B (16KB)
#define GEMM_SMEM (STAGES * STAGE_BYTES)   // 98304

__global__ void __launch_bounds__(256) mma_gemm(
    int K,
    const __nv_bfloat16* __restrict__ A, long sA,
    const __nv_bfloat16* __restrict__ B, long sB,
    float* __restrict__ C, int ldc, long sC,
    const float* __restrict__ bias, long sBias)
{
    extern __shared__ char smem[];
    const uint32_t sb = s2u(smem);
    const int tid = threadIdx.x;
    const int wid = tid >> 5, lane = tid & 31;
    const int bz = blockIdx.z;
    const int row0 = blockIdx.y * 128;
    const int col0 = blockIdx.x * 128;
    A += (long)bz * sA;
    B += (long)bz * sB;
    C += (long)bz * sC;

    const int warp_m = (wid & 3) * 32;
    const int warp_n = (wid >> 2) * 64;

    float acc[2][8][4];
#pragma unroll
    for (int mi = 0; mi < 2; mi++)
#pragma unroll
        for (int ni = 0; ni < 8; ni++)
#pragma unroll
            for (int q = 0; q < 4; q++) acc[mi][ni][q] = 0.f;

    const int NC = K / KCH;

    auto load_chunk = [&](int c, int s) {
        uint32_t ab = sb + s * STAGE_BYTES;
        uint32_t bb = ab + STAGE_A;
        long k0 = (long)c * KCH;
#pragma unroll
        for (int i = 0; i < 8; i++) {
            int idx = tid + i * 256;
            if (idx < 1024) {                     // A: 128 rows x 8 chunks of 16B
                int r = idx >> 3, cj = idx & 7;
                cp16(ab + SWZ(r * 128 + cj * 16), A + (long)(row0 + r) * K + k0 + cj * 8);
            } else {                              // B: 128 rows x 8 chunks
                int j = idx - 1024;
                int r = j >> 3, cj = j & 7;
                cp16(bb + SWZ(r * 128 + cj * 16), B + (long)(col0 + r) * K + k0 + cj * 8);
            }
        }
    };

    // ldmatrix lane addressing: 16 rows x two 16B column-chunks
    const int lrow = lane & 15;
    const int lcol = (lane >> 4) * 16;

    load_chunk(0, 0);
    asm volatile("cp.async.commit_group;" ::: "memory");
    if (NC > 1) load_chunk(1, 1);
    asm volatile("cp.async.commit_group;" ::: "memory");

    for (int c = 0; c < NC; c++) {
        if (c + 2 < NC) load_chunk(c + 2, (c + 2) % STAGES);
        asm volatile("cp.async.commit_group;" ::: "memory");
        asm volatile("cp.async.wait_group 2;" ::: "memory");
        __syncthreads();

        uint32_t ab = sb + (c % STAGES) * STAGE_BYTES;
        uint32_t bb = ab + STAGE_A;
#pragma unroll
        for (int ks = 0; ks < 4; ks++) {
            uint32_t af[2][4];
#pragma unroll
            for (int mi = 0; mi < 2; mi++) {
                uint32_t addr = ab + SWZ((warp_m + mi * 16 + lrow) * 128 + ks * 32 + lcol);
                ldsm4(af[mi][0], af[mi][1], af[mi][2], af[mi][3], addr);
            }
            uint32_t bf[8][2];
#pragma unroll
            for (int nb = 0; nb < 4; nb++) {
                uint32_t r0, r1, r2, r3;
                uint32_t addr = bb + SWZ((warp_n + nb * 16 + lrow) * 128 + ks * 32 + lcol);
                ldsm4(r0, r1, r2, r3, addr);
                bf[2 * nb][0] = r0; bf[2 * nb][1] = r2;
                bf[2 * nb + 1][0] = r1; bf[2 * nb + 1][1] = r3;
            }
#pragma unroll
            for (int mi = 0; mi < 2; mi++)
#pragma unroll
                for (int ni = 0; ni < 8; ni++)
                    mma16816(acc[mi][ni], af[mi], bf[ni][0], bf[ni][1]);
        }
        __syncthreads();
    }

    // epilogue: thread (lane) holds rows lane/4 (+8), col pairs (lane%4)*2
    const int cbase = col0 + warp_n + (lane & 3) * 2;
#pragma unroll
    for (int mi = 0; mi < 2; mi++) {
#pragma unroll
        for (int h = 0; h < 2; h++) {
            int row = row0 + warp_m + mi * 16 + (lane >> 2) + h * 8;
            float* cr = C + (long)row * ldc + cbase;
            if (bias) {
                const float* bp = bias + bz * sBias + cbase;
#pragma unroll
                for (int ni = 0; ni < 8; ni++) {
                    float2 v;
                    v.x = acc[mi][ni][h * 2]     + bp[ni * 8];
                    v.y = acc[mi][ni][h * 2 + 1] + bp[ni * 8 + 1];
                    *(float2*)(cr + ni * 8) = v;
                }
            } else {
#pragma unroll
                for (int ni = 0; ni < 8; ni++) {
                    float2 v;
                    v.x = acc[mi][ni][h * 2];
                    v.y = acc[mi][ni][h * 2 + 1];
                    *(float2*)(cr + ni * 8) = v;
                }
            }
        }
    }
}

// ---------------- fp32 -> bf16x3 split conversions --------------------------
// patA: [hi, lo, hi]; patB: [hi, hi, lo]
__global__ void split_kernel(const float* __restrict__ src, long sS,
                             __nv_bfloat16* __restrict__ dst, long sD,
                             int total, int C, int patB)
{
    int b = blockIdx.y;
    src += (long)b * sS;
    dst += (long)b * sD;
    for (int idx = blockIdx.x * 256 + threadIdx.x; idx < total; idx += gridDim.x * 256) {
        int rr = idx / C, cc = idx % C;
        float x = src[idx];
        __nv_bfloat16 h = __float2bfloat16(x);
        __nv_bfloat16 l = __float2bfloat16(x - __bfloat162float(h));
        __nv_bfloat16* d = dst + (long)rr * (3 * C) + 3 * cc;
        if (patB) { d[0] = h; d[1] = h; d[2] = l; }
        else      { d[0] = h; d[1] = l; d[2] = h; }
    }
}

// transpose + split: src [R,C] -> dst [C, 3R]; writes patA and/or patB copies
__global__ void tsplit_kernel(const float* __restrict__ src, long sS,
                              __nv_bfloat16* __restrict__ dstA,
                              __nv_bfloat16* __restrict__ dstB,
                              long sD, int R, int C)
{
    __shared__ float t[32][33];
    int b = blockIdx.z;
    src += (long)b * sS;
    int r0 = blockIdx.y * 32, c0 = blockIdx.x * 32;
    int tx = threadIdx.x, ty = threadIdx.y;   // (32, 8)
#pragma unroll
    for (int i = 0; i < 4; i++)
        t[ty + 8 * i][tx] = src[(long)(r0 + ty + 8 * i) * C + c0 + tx];
    __syncthreads();
#pragma unroll
    for (int i = 0; i < 4; i++) {
        int cc = c0 + ty + 8 * i;
        int rr = r0 + tx;
        float x = t[tx][ty + 8 * i];
        __nv_bfloat16 h = __float2bfloat16(x);
        __nv_bfloat16 l = __float2bfloat16(x - __bfloat162float(h));
        long o = (long)b * sD + (long)cc * (3 * R) + 3 * rr;
        if (dstA) { dstA[o] = h; dstA[o + 1] = l; dstA[o + 2] = h; }
        if (dstB) { dstB[o] = h; dstB[o + 1] = h; dstB[o + 2] = l; }
    }
}

// ---------------- small helper kernels --------------------------------------
__device__ __forceinline__ float warpSum(float v) {
#pragma unroll
    for (int o = 16; o; o >>= 1) v += __shfl_xor_sync(0xffffffffu, v, o);
    return v;
}

__global__ void colsum_kernel(const float* __restrict__ X, float* __restrict__ s) {
    int b = blockIdx.x, m = threadIdx.x;
    const float* xb = X + (long)b * Nn * LO;
    float acc = 0.f;
    for (int n = 0; n < Nn; n++) acc += xb[(long)n * LO + m];
    s[b * LO + m] = acc;
}

__global__ void rowdot_kernel(const float* __restrict__ W, const float* __restrict__ x,
                              float* __restrict__ out, int rows, int cols,
                              const float* __restrict__ addv) {
    int warp = threadIdx.x >> 5, lane = threadIdx.x & 31;
    int r = blockIdx.x * 8 + warp;
    int b = blockIdx.y;
    if (r >= rows) return;
    const float* xb = x + (long)b * cols;
    const float* wr = W + (long)r * cols;
    float s = 0.f;
    for (int c = lane; c < cols; c += 32) s += wr[c] * xb[c];
    s = warpSum(s);
    if (lane == 0) out[(long)b * rows + r] = s + (addv ? addv[r] : 0.f);
}

__global__ void wvec_kernel(const float* __restrict__ Amat, const float* __restrict__ bv,
                            float* __restrict__ w) {
    int h = blockIdx.x * 256 + threadIdx.x;
    int b = blockIdx.y;
    const float* Ab = Amat + (long)b * LO * HI;
    float acc = 0.f;
    for (int l = 0; l < LO; l++) acc += bv[l] * Ab[(long)l * HI + h];
    w[(long)b * HI + h] = acc;
}

// ---------------- fused softmax + min-max-norm attention combine ------------
__global__ void __launch_bounds__(256) attn_kernel(
    float* __restrict__ E, const int* __restrict__ linkage,
    const float* __restrict__ u, const float* __restrict__ bq,
    const float* __restrict__ v, const float* __restrict__ bk)
{
    __shared__ float red[8];
    const int l = blockIdx.x, b = blockIdx.y;
    float* row = E + ((long)(b * LO + l)) * HI;
    const int* lrow = linkage + (long)l * HI;
    const float* vb = v + (long)b * HI;
    const float uval = u[b * LO + l];
    const float bqv  = bq[l];

    float ev[16];
    unsigned mbits = 0;
    float gmax = -3.4e38f, mn = BIGF, mx = -BIGF;

#pragma unroll
    for (int j = 0; j < 16; j++) {
        int h = threadIdx.x + j * 256;
        float bkh = bk[h];
        float e = (row[h] + uval * bkh + bqv * (vb[h] + (float)Nn * bkh)) * 0.015625f;
        ev[j] = e;
        gmax = fmaxf(gmax, e);
        if (lrow[h] > 0) {
            mbits |= 1u << j;
            mn = fminf(mn, e);
            mx = fmaxf(mx, e);
        }
    }

    const int wid = threadIdx.x >> 5, lane = threadIdx.x & 31;
#pragma unroll
    for (int o = 16; o; o >>= 1) gmax = fmaxf(gmax, __shfl_xor_sync(0xffffffffu, gmax, o));
    if (lane == 0) red[wid] = gmax;
    __syncthreads();
    gmax = red[0];
#pragma unroll
    for (int i = 1; i < 8; i++) gmax = fmaxf(gmax, red[i]);
    __syncthreads();

#pragma unroll
    for (int o = 16; o; o >>= 1) mn = fminf(mn, __shfl_xor_sync(0xffffffffu, mn, o));
    if (lane == 0) red[wid] = mn;
    __syncthreads();
    mn = red[0];
#pragma unroll
    for (int i = 1; i < 8; i++) mn = fminf(mn, red[i]);
    __syncthreads();

#pragma unroll
    for (int o = 16; o; o >>= 1) mx = fmaxf(mx, __shfl_xor_sync(0xffffffffu, mx, o));
    if (lane == 0) red[wid] = mx;
    __syncthreads();
    mx = red[0];
#pragma unroll
    for (int i = 1; i < 8; i++) mx = fmaxf(mx, red[i]);
    __syncthreads();

    float den = mx - mn;
    if (den == 0.0f) den = 1e-6f;
    const bool hasMask = (mx != -BIGF);
    const float lmax = hasMask ? (((mx - mn) == 0.0f) ? 0.0f : 1.0f) : -BIGF;

    float eg[16], el[16];
    float gsum = 0.f, lsum = 0.f;
#pragma unroll
    for (int j = 0; j < 16; j++) {
        float e = ev[j];
        float g = __expf(e - gmax);
        eg[j] = g;
        gsum += g;
        float lv = ((mbits >> j) & 1) ? (e - mn) / den : -BIGF;
        float ll = __expf(lv - lmax);
        el[j] = ll;
        lsum += ll;
    }

    gsum = warpSum(gsum);
    if (lane == 0) red[wid] = gsum;
    __syncthreads();
    gsum = red[0];
#pragma unroll
    for (int i = 1; i < 8; i++) gsum += red[i];
    __syncthreads();

    lsum = warpSum(lsum);
    if (lane == 0) red[wid] = lsum;
    __syncthreads();
    lsum = red[0];
#pragma unroll
    for (int i = 1; i < 8; i++) lsum += red[i];

    const float rg = 1.0f / gsum, rl = 1.0f / lsum;
#pragma unroll
    for (int j = 0; j < 16; j++) {
        int h = threadIdx.x + j * 256;
        row[h] = eg[j] * rg + el[j] * rl;
    }
}

// ---------------- host launch ------------------------------------------------
template <typename T>
static T* symaddr(const void* sym) {
    void* p = nullptr;
    cudaGetSymbolAddress(&p, sym);
    return (T*)p;
}

extern "C" void kernel_launch(void* const* d_in, const int* in_sizes, int n_in,
                              void* d_out, int out_size) {
    const float* X   = (const float*)d_in[0];
    const int*   lk  = (const int*)d_in[1];
    const float* wq  = (const float*)d_in[2];
    const float* bq  = (const float*)d_in[3];
    const float* wk  = (const float*)d_in[4];
    const float* bk  = (const float*)d_in[5];
    const float* wv  = (const float*)d_in[6];
    const float* bv  = (const float*)d_in[7];
    const float* ow  = (const float*)d_in[8];
    const float* ob  = (const float*)d_in[9];
    float* out = (float*)d_out;

    float* G = symaddr<float>(g_G);
    float* T = symaddr<float>(g_T);
    float* E = symaddr<float>(g_E);
    float* P = symaddr<float>(g_P);
    float* R = symaddr<float>(g_R);
    float* s = symaddr<float>(g_s);
    float* u = symaddr<float>(g_u);
    float* v = symaddr<float>(g_v);
    float* w = symaddr<float>(g_w);
    float* z = symaddr<float>(g_z);

    __nv_bfloat16* XtA  = symaddr<__nv_bfloat16>(g_XtA);
    __nv_bfloat16* XtB  = symaddr<__nv_bfloat16>(g_XtB);
    __nv_bfloat16* WqA  = symaddr<__nv_bfloat16>(g_WqA);
    __nv_bfloat16* GB   = symaddr<__nv_bfloat16>(g_GB);
    __nv_bfloat16* TA   = symaddr<__nv_bfloat16>(g_TA);
    __nv_bfloat16* WkB  = symaddr<__nv_bfloat16>(g_WkB);
    __nv_bfloat16* WvTA = symaddr<__nv_bfloat16>(g_WvTA);
    __nv_bfloat16* AtB  = symaddr<__nv_bfloat16>(g_AtB);
    __nv_bfloat16* PA   = symaddr<__nv_bfloat16>(g_PA);
    __nv_bfloat16* OB   = symaddr<__nv_bfloat16>(g_OB);
    __nv_bfloat16* RtB  = symaddr<__nv_bfloat16>(g_RtB);
    __nv_bfloat16* XA   = symaddr<__nv_bfloat16>(g_XA);

    cudaFuncSetAttribute(mma_gemm, cudaFuncAttributeMaxDynamicSharedMemorySize, GEMM_SMEM);

    dim3 tb(32, 8);

    // input/weight conversions
    tsplit_kernel<<<dim3(LO/32, Nn/32, Bb), tb>>>(X, (long)Nn*LO, XtA, XtB, (long)LO*K1, Nn, LO);
    split_kernel<<<dim3(1024, 1), 256>>>(wq, 0, WqA, 0, LO*LO, LO, 0);
    split_kernel<<<dim3(8192, 1), 256>>>(wk, 0, WkB, 0, HI*LO, LO, 1);
    tsplit_kernel<<<dim3(LO/32, LO/32, 1), tb>>>(wv, 0, WvTA, nullptr, 0, LO, LO);
    split_kernel<<<dim3(16384, 1), 256>>>(ow, 0, OB, 0, HI*HI, HI, 1);
    split_kernel<<<dim3(4096, Bb), 256>>>(X, (long)Nn*LO, XA, (long)Nn*K2, Nn*LO, LO, 0);

    // bias correction vectors (exact; zero-valued in this dataset)
    colsum_kernel<<<Bb, LO>>>(X, s);
    rowdot_kernel<<<dim3(LO/8, Bb), 256>>>(wq, s, u, LO, LO, nullptr);
    rowdot_kernel<<<dim3(HI/8, Bb), 256>>>(wk, s, v, HI, LO, nullptr);

    // G_b = Xt Xt^T   [512,512] K'=6144
    mma_gemm<<<dim3(LO/128, LO/128, Bb), 256, GEMM_SMEM>>>(
        K1, XtA, (long)LO*K1, XtB, (long)LO*K1, G, LO, (long)LO*LO, nullptr, 0);
    split_kernel<<<dim3(1024, Bb), 256>>>(G, (long)LO*LO, GB, (long)LO*K2, LO*LO, LO, 1);

    // T_b = Wq G_b    (G symmetric => B rows are G rows)
    mma_gemm<<<dim3(LO/128, LO/128, Bb), 256, GEMM_SMEM>>>(
        K2, WqA, 0, GB, (long)LO*K2, T, LO, (long)LO*LO, nullptr, 0);
    split_kernel<<<dim3(1024, Bb), 256>>>(T, (long)LO*LO, TA, (long)LO*K2, LO*LO, LO, 0);

    // E_b = T_b Wk^T  [512,4096]
    mma_gemm<<<dim3(HI/128, LO/128, Bb), 256, GEMM_SMEM>>>(
        K2, TA, (long)LO*K2, WkB, 0, E, HI, (long)LO*HI, nullptr, 0);

    // A_b = softmax(e) + softmax(minmaxnorm(e, mask)), in place in E
    attn_kernel<<<dim3(LO, Bb), 256>>>(E, lk, u, bq, v, bk);

    // bias path: w_b = bv^T A_b ; z_b = w_b O^T + o_b
    wvec_kernel<<<dim3(HI/256, Bb), 256>>>(E, bv, w);
    rowdot_kernel<<<dim3(HI/8, Bb), 256>>>(ow, w, z, HI, HI, ob);

    // P_b = Wv^T A_b  (B operand is A^T, via transpose-split)
    tsplit_kernel<<<dim3(HI/32, LO/32, Bb), tb>>>(E, (long)LO*HI, nullptr, AtB, (long)HI*K2, LO, HI);
    mma_gemm<<<dim3(HI/128, LO/128, Bb), 256, GEMM_SMEM>>>(
        K2, WvTA, 0, AtB, (long)HI*K2, P, HI, (long)LO*HI, nullptr, 0);

    // R_b = P_b O^T   [512,4096] K'=12288 (dominant)
    split_kernel<<<dim3(8192, Bb), 256>>>(P, (long)LO*HI, PA, (long)LO*K5, LO*HI, HI, 0);
    mma_gemm<<<dim3(HI/128, LO/128, Bb), 256, GEMM_SMEM>>>(
        K5, PA, (long)LO*K5, OB, 0, R, HI, (long)LO*HI, nullptr, 0);

    // out_b = X_b R_b + z_b  [2048,4096] (B operand is R^T)
    tsplit_kernel<<<dim3(HI/32, LO/32, Bb), tb>>>(R, (long)LO*HI, nullptr, RtB, (long)HI*K2, LO, HI);
    mma_gemm<<<dim3(HI/128, Nn/128, Bb), 256, GEMM_SMEM>>>(
        K2, XA, (long)Nn*K2, RtB, (long)HI*K2, out, HI, (long)Nn*HI, z, HI);

    (void)in_sizes; (void)n_in; (void)out_size;
}

// round 8
// speedup vs baseline: 3.0295x; 1.1027x over previous
#include <cuda_runtime.h>
#include <cuda_bf16.h>
#include <cstdint>

// Shapes (fixed by the problem): B=8, N=2048, low=512, high=4096
#define Bb 8
#define Nn 2048
#define LO 512
#define HI 4096
#define BIGF 9.0e15f

// ---------------- fp32 scratch --------------------------------------------
__device__ float g_G[Bb*LO*LO];
__device__ float g_T[Bb*LO*LO];
__device__ float g_E[Bb*LO*HI];
__device__ float g_P[Bb*LO*HI];
__device__ float g_R[Bb*LO*HI];
__device__ float g_s[Bb*LO];
__device__ float g_u[Bb*LO];
__device__ float g_v[Bb*HI];
__device__ float g_w[Bb*HI];
__device__ float g_z[Bb*HI];

// ---------------- bf16 hi/lo operands (K-major, original K) ----------------
__device__ __align__(256) __nv_bfloat16 g_XtH[Bb*LO*Nn];
__device__ __align__(256) __nv_bfloat16 g_XtL[Bb*LO*Nn];
__device__ __align__(256) __nv_bfloat16 g_WqH[LO*LO];
__device__ __align__(256) __nv_bfloat16 g_WqL[LO*LO];
__device__ __align__(256) __nv_bfloat16 g_GH [Bb*LO*LO];
__device__ __align__(256) __nv_bfloat16 g_GL [Bb*LO*LO];
__device__ __align__(256) __nv_bfloat16 g_TH [Bb*LO*LO];
__device__ __align__(256) __nv_bfloat16 g_TL [Bb*LO*LO];
__device__ __align__(256) __nv_bfloat16 g_WkH[HI*LO];
__device__ __align__(256) __nv_bfloat16 g_WkL[HI*LO];
__device__ __align__(256) __nv_bfloat16 g_WvTH[LO*LO];
__device__ __align__(256) __nv_bfloat16 g_WvTL[LO*LO];
__device__ __align__(256) __nv_bfloat16 g_AtH[Bb*HI*LO];
__device__ __align__(256) __nv_bfloat16 g_AtL[Bb*HI*LO];
__device__ __align__(256) __nv_bfloat16 g_PH [Bb*LO*HI];
__device__ __align__(256) __nv_bfloat16 g_PL [Bb*LO*HI];
__device__ __align__(256) __nv_bfloat16 g_OH [HI*HI];
__device__ __align__(256) __nv_bfloat16 g_OL [HI*HI];
__device__ __align__(256) __nv_bfloat16 g_RtH[Bb*HI*LO];
__device__ __align__(256) __nv_bfloat16 g_RtL[Bb*HI*LO];
__device__ __align__(256) __nv_bfloat16 g_XH [Bb*Nn*LO];
__device__ __align__(256) __nv_bfloat16 g_XL [Bb*Nn*LO];

// ---------------- PTX helpers ----------------------------------------------
__device__ __forceinline__ uint32_t s2u(const void* p) {
    uint32_t a;
    asm("{ .reg .u64 t; cvta.to.shared.u64 t, %1; cvt.u32.u64 %0, t; }" : "=r"(a) : "l"(p));
    return a;
}
#define SWZ(x) ((x) ^ (((x) >> 3) & 0x70))

__device__ __forceinline__ void cp16(uint32_t sa, const void* ga) {
    asm volatile("cp.async.cg.shared.global [%0], [%1], 16;" :: "r"(sa), "l"(ga));
}

__device__ __forceinline__ void ldsm4(uint32_t& r0, uint32_t& r1, uint32_t& r2,
                                      uint32_t& r3, uint32_t a) {
    asm volatile("ldmatrix.sync.aligned.m8n8.x4.shared.b16 {%0,%1,%2,%3}, [%4];"
        : "=r"(r0), "=r"(r1), "=r"(r2), "=r"(r3) : "r"(a));
}

__device__ __forceinline__ void mma16816(float* d, const uint32_t* a,
                                         uint32_t b0, uint32_t b1) {
    asm volatile(
        "mma.sync.aligned.m16n8k16.row.col.f32.bf16.bf16.f32 "
        "{%0,%1,%2,%3}, {%4,%5,%6,%7}, {%8,%9}, {%0,%1,%2,%3};"
        : "+f"(d[0]), "+f"(d[1]), "+f"(d[2]), "+f"(d[3])
        : "r"(a[0]), "r"(a[1]), "r"(a[2]), "r"(a[3]), "r"(b0), "r"(b1));
}

// ---------------- HMMA GEMM: C = Ah·Bh^T + Al·Bh^T + Ah·Bl^T ---------------
// CTA tile 128x128, 8 warps (warp tile 32x64), K-chunk 64, 3-stage cp.async.
// All operands K-major [rows x K], K multiple of 64.
#define STAGES 3
#define KCH 64
#define STAGE_T 16384                 // one 128x64 bf16 tile
#define STAGE_BYTES 65536             // Ahi + Alo + Bhi + Blo
#define GEMM_SMEM (STAGES * STAGE_BYTES)   // 196608

__global__ void __launch_bounds__(256) mma_gemm(
    int K,
    const __nv_bfloat16* __restrict__ Ahi, const __nv_bfloat16* __restrict__ Alo, long sA,
    const __nv_bfloat16* __restrict__ Bhi, const __nv_bfloat16* __restrict__ Blo, long sB,
    float* __restrict__ C, int ldc, long sC,
    const float* __restrict__ bias, long sBias)
{
    extern __shared__ char smem[];
    const uint32_t sb = s2u(smem);
    const int tid = threadIdx.x;
    const int wid = tid >> 5, lane = tid & 31;
    const int bz = blockIdx.z;
    const int row0 = blockIdx.y * 128;
    const int col0 = blockIdx.x * 128;
    Ahi += (long)bz * sA; Alo += (long)bz * sA;
    Bhi += (long)bz * sB; Blo += (long)bz * sB;
    C += (long)bz * sC;

    const int warp_m = (wid & 3) * 32;
    const int warp_n = (wid >> 2) * 64;

    float acc[2][8][4];
#pragma unroll
    for (int mi = 0; mi < 2; mi++)
#pragma unroll
        for (int ni = 0; ni < 8; ni++)
#pragma unroll
            for (int q = 0; q < 4; q++) acc[mi][ni][q] = 0.f;

    const int NC = K / KCH;

    auto load_chunk = [&](int c, int s) {
        uint32_t st = sb + s * STAGE_BYTES;
        long k0 = (long)c * KCH;
#pragma unroll
        for (int i = 0; i < 16; i++) {
            int idx = tid + i * 256;          // 0..4095
            int t = i >> 2;                   // tile 0..3 (compile-time per iter)
            int j = idx & 1023;
            int r = j >> 3, cj = j & 7;
            const __nv_bfloat16* src = (t == 0) ? Ahi : (t == 1) ? Alo
                                     : (t == 2) ? Bhi : Blo;
            int rb = (t < 2) ? row0 : col0;
            cp16(st + t * STAGE_T + SWZ(r * 128 + cj * 16),
                 src + (long)(rb + r) * K + k0 + cj * 8);
        }
    };

    // ldmatrix lane addressing: 16 rows x two 16B column-chunks
    const int lrow = lane & 15;
    const int lcol = (lane >> 4) * 16;

    load_chunk(0, 0);
    asm volatile("cp.async.commit_group;" ::: "memory");
    if (NC > 1) load_chunk(1, 1);
    asm volatile("cp.async.commit_group;" ::: "memory");

    for (int c = 0; c < NC; c++) {
        if (c + 2 < NC) load_chunk(c + 2, (c + 2) % STAGES);
        asm volatile("cp.async.commit_group;" ::: "memory");
        asm volatile("cp.async.wait_group 2;" ::: "memory");
        __syncthreads();

        uint32_t st = sb + (c % STAGES) * STAGE_BYTES;
        uint32_t ahb = st, alb = st + STAGE_T;
        uint32_t bhb = st + 2 * STAGE_T, blb = st + 3 * STAGE_T;
#pragma unroll
        for (int ks = 0; ks < 4; ks++) {
            uint32_t afh[2][4], afl[2][4], bfh[8][2], bfl[8][2];
#pragma unroll
            for (int mi = 0; mi < 2; mi++) {
                uint32_t off = SWZ((warp_m + mi * 16 + lrow) * 128 + ks * 32 + lcol);
                ldsm4(afh[mi][0], afh[mi][1], afh[mi][2], afh[mi][3], ahb + off);
                ldsm4(afl[mi][0], afl[mi][1], afl[mi][2], afl[mi][3], alb + off);
            }
#pragma unroll
            for (int nb = 0; nb < 4; nb++) {
                uint32_t off = SWZ((warp_n + nb * 16 + lrow) * 128 + ks * 32 + lcol);
                uint32_t r0, r1, r2, r3;
                ldsm4(r0, r1, r2, r3, bhb + off);
                bfh[2 * nb][0] = r0; bfh[2 * nb][1] = r2;
                bfh[2 * nb + 1][0] = r1; bfh[2 * nb + 1][1] = r3;
                ldsm4(r0, r1, r2, r3, blb + off);
                bfl[2 * nb][0] = r0; bfl[2 * nb][1] = r2;
                bfl[2 * nb + 1][0] = r1; bfl[2 * nb + 1][1] = r3;
            }
#pragma unroll
            for (int mi = 0; mi < 2; mi++)
#pragma unroll
                for (int ni = 0; ni < 8; ni++)
                    mma16816(acc[mi][ni], afh[mi], bfh[ni][0], bfh[ni][1]);
#pragma unroll
            for (int mi = 0; mi < 2; mi++)
#pragma unroll
                for (int ni = 0; ni < 8; ni++)
                    mma16816(acc[mi][ni], afl[mi], bfh[ni][0], bfh[ni][1]);
#pragma unroll
            for (int mi = 0; mi < 2; mi++)
#pragma unroll
                for (int ni = 0; ni < 8; ni++)
                    mma16816(acc[mi][ni], afh[mi], bfl[ni][0], bfl[ni][1]);
        }
        __syncthreads();
    }

    // epilogue: thread (lane) holds rows lane/4 (+8), col pairs (lane%4)*2
    const int cbase = col0 + warp_n + (lane & 3) * 2;
#pragma unroll
    for (int mi = 0; mi < 2; mi++) {
#pragma unroll
        for (int h = 0; h < 2; h++) {
            int row = row0 + warp_m + mi * 16 + (lane >> 2) + h * 8;
            float* cr = C + (long)row * ldc + cbase;
            if (bias) {
                const float* bp = bias + bz * sBias + cbase;
#pragma unroll
                for (int ni = 0; ni < 8; ni++) {
                    float2 v;
                    v.x = acc[mi][ni][h * 2]     + bp[ni * 8];
                    v.y = acc[mi][ni][h * 2 + 1] + bp[ni * 8 + 1];
                    *(float2*)(cr + ni * 8) = v;
                }
            } else {
#pragma unroll
                for (int ni = 0; ni < 8; ni++) {
                    float2 v;
                    v.x = acc[mi][ni][h * 2];
                    v.y = acc[mi][ni][h * 2 + 1];
                    *(float2*)(cr + ni * 8) = v;
                }
            }
        }
    }
}

// ---------------- fp32 -> bf16 hi/lo split (same layout, coalesced) ---------
__global__ void split2_kernel(const float* __restrict__ src, long sS,
                              __nv_bfloat16* __restrict__ hi,
                              __nv_bfloat16* __restrict__ lo,
                              long sD, int pairs)
{
    int b = blockIdx.y;
    const float2* s2 = (const float2*)(src + (long)b * sS);
    uint32_t* h2 = (uint32_t*)(hi + (long)b * sD);
    uint32_t* l2 = (uint32_t*)(lo + (long)b * sD);
    for (int i = blockIdx.x * 256 + threadIdx.x; i < pairs; i += gridDim.x * 256) {
        float2 x = s2[i];
        __nv_bfloat16 h0 = __float2bfloat16(x.x);
        __nv_bfloat16 h1 = __float2bfloat16(x.y);
        __nv_bfloat16 l0 = __float2bfloat16(x.x - __bfloat162float(h0));
        __nv_bfloat16 l1 = __float2bfloat16(x.y - __bfloat162float(h1));
        uint32_t hv = (uint32_t)*(uint16_t*)&h0 | ((uint32_t)*(uint16_t*)&h1 << 16);
        uint32_t lv = (uint32_t)*(uint16_t*)&l0 | ((uint32_t)*(uint16_t*)&l1 << 16);
        h2[i] = hv;
        l2[i] = lv;
    }
}

// transpose + split: src [R,C] -> hi/lo [C,R] (K-major over r)
__global__ void tsplit2_kernel(const float* __restrict__ src, long sS,
                               __nv_bfloat16* __restrict__ hi,
                               __nv_bfloat16* __restrict__ lo,
                               long sD, int R, int C)
{
    __shared__ float t[32][33];
    int b = blockIdx.z;
    src += (long)b * sS;
    int r0 = blockIdx.y * 32, c0 = blockIdx.x * 32;
    int tx = threadIdx.x, ty = threadIdx.y;   // (32, 8)
#pragma unroll
    for (int i = 0; i < 4; i++)
        t[ty + 8 * i][tx] = src[(long)(r0 + ty + 8 * i) * C + c0 + tx];
    __syncthreads();
#pragma unroll
    for (int i = 0; i < 4; i++) {
        int cc = c0 + ty + 8 * i;
        int rr = r0 + tx;
        float x = t[tx][ty + 8 * i];
        __nv_bfloat16 h = __float2bfloat16(x);
        __nv_bfloat16 l = __float2bfloat16(x - __bfloat162float(h));
        long o = (long)b * sD + (long)cc * R + rr;
        hi[o] = h;
        lo[o] = l;
    }
}

// ---------------- small helper kernels --------------------------------------
__device__ __forceinline__ float warpSum(float v) {
#pragma unroll
    for (int o = 16; o; o >>= 1) v += __shfl_xor_sync(0xffffffffu, v, o);
    return v;
}

__global__ void colsum_kernel(const float* __restrict__ X, float* __restrict__ s) {
    int b = blockIdx.x, m = threadIdx.x;
    const float* xb = X + (long)b * Nn * LO;
    float acc = 0.f;
    for (int n = 0; n < Nn; n++) acc += xb[(long)n * LO + m];
    s[b * LO + m] = acc;
}

__global__ void rowdot_kernel(const float* __restrict__ W, const float* __restrict__ x,
                              float* __restrict__ out, int rows, int cols,
                              const float* __restrict__ addv) {
    int warp = threadIdx.x >> 5, lane = threadIdx.x & 31;
    int r = blockIdx.x * 8 + warp;
    int b = blockIdx.y;
    if (r >= rows) return;
    const float* xb = x + (long)b * cols;
    const float* wr = W + (long)r * cols;
    float s = 0.f;
    for (int c = lane; c < cols; c += 32) s += wr[c] * xb[c];
    s = warpSum(s);
    if (lane == 0) out[(long)b * rows + r] = s + (addv ? addv[r] : 0.f);
}

__global__ void wvec_kernel(const float* __restrict__ Amat, const float* __restrict__ bv,
                            float* __restrict__ w) {
    int h = blockIdx.x * 256 + threadIdx.x;
    int b = blockIdx.y;
    const float* Ab = Amat + (long)b * LO * HI;
    float acc = 0.f;
    for (int l = 0; l < LO; l++) acc += bv[l] * Ab[(long)l * HI + h];
    w[(long)b * HI + h] = acc;
}

// ---------------- fused softmax + min-max-norm attention combine ------------
__global__ void __launch_bounds__(256) attn_kernel(
    float* __restrict__ E, const int* __restrict__ linkage,
    const float* __restrict__ u, const float* __restrict__ bq,
    const float* __restrict__ v, const float* __restrict__ bk)
{
    __shared__ float red[8];
    const int l = blockIdx.x, b = blockIdx.y;
    float* row = E + ((long)(b * LO + l)) * HI;
    const int* lrow = linkage + (long)l * HI;
    const float* vb = v + (long)b * HI;
    const float uval = u[b * LO + l];
    const float bqv  = bq[l];

    float ev[16];
    unsigned mbits = 0;
    float gmax = -3.4e38f, mn = BIGF, mx = -BIGF;

#pragma unroll
    for (int j = 0; j < 16; j++) {
        int h = threadIdx.x + j * 256;
        float bkh = bk[h];
        float e = (row[h] + uval * bkh + bqv * (vb[h] + (float)Nn * bkh)) * 0.015625f;
        ev[j] = e;
        gmax = fmaxf(gmax, e);
        if (lrow[h] > 0) {
            mbits |= 1u << j;
            mn = fminf(mn, e);
            mx = fmaxf(mx, e);
        }
    }

    const int wid = threadIdx.x >> 5, lane = threadIdx.x & 31;
#pragma unroll
    for (int o = 16; o; o >>= 1) gmax = fmaxf(gmax, __shfl_xor_sync(0xffffffffu, gmax, o));
    if (lane == 0) red[wid] = gmax;
    __syncthreads();
    gmax = red[0];
#pragma unroll
    for (int i = 1; i < 8; i++) gmax = fmaxf(gmax, red[i]);
    __syncthreads();

#pragma unroll
    for (int o = 16; o; o >>= 1) mn = fminf(mn, __shfl_xor_sync(0xffffffffu, mn, o));
    if (lane == 0) red[wid] = mn;
    __syncthreads();
    mn = red[0];
#pragma unroll
    for (int i = 1; i < 8; i++) mn = fminf(mn, red[i]);
    __syncthreads();

#pragma unroll
    for (int o = 16; o; o >>= 1) mx = fmaxf(mx, __shfl_xor_sync(0xffffffffu, mx, o));
    if (lane == 0) red[wid] = mx;
    __syncthreads();
    mx = red[0];
#pragma unroll
    for (int i = 1; i < 8; i++) mx = fmaxf(mx, red[i]);
    __syncthreads();

    float den = mx - mn;
    if (den == 0.0f) den = 1e-6f;
    const bool hasMask = (mx != -BIGF);
    const float lmax = hasMask ? (((mx - mn) == 0.0f) ? 0.0f : 1.0f) : -BIGF;

    float eg[16], el[16];
    float gsum = 0.f, lsum = 0.f;
#pragma unroll
    for (int j = 0; j < 16; j++) {
        float e = ev[j];
        float g = __expf(e - gmax);
        eg[j] = g;
        gsum += g;
        float lv = ((mbits >> j) & 1) ? (e - mn) / den : -BIGF;
        float ll = __expf(lv - lmax);
        el[j] = ll;
        lsum += ll;
    }

    gsum = warpSum(gsum);
    if (lane == 0) red[wid] = gsum;
    __syncthreads();
    gsum = red[0];
#pragma unroll
    for (int i = 1; i < 8; i++) gsum += red[i];
    __syncthreads();

    lsum = warpSum(lsum);
    if (lane == 0) red[wid] = lsum;
    __syncthreads();
    lsum = red[0];
#pragma unroll
    for (int i = 1; i < 8; i++) lsum += red[i];

    const float rg = 1.0f / gsum, rl = 1.0f / lsum;
#pragma unroll
    for (int j = 0; j < 16; j++) {
        int h = threadIdx.x + j * 256;
        row[h] = eg[j] * rg + el[j] * rl;
    }
}

// ---------------- host launch ------------------------------------------------
template <typename T>
static T* symaddr(const void* sym) {
    void* p = nullptr;
    cudaGetSymbolAddress(&p, sym);
    return (T*)p;
}

extern "C" void kernel_launch(void* const* d_in, const int* in_sizes, int n_in,
                              void* d_out, int out_size) {
    const float* X   = (const float*)d_in[0];
    const int*   lk  = (const int*)d_in[1];
    const float* wq  = (const float*)d_in[2];
    const float* bq  = (const float*)d_in[3];
    const float* wk  = (const float*)d_in[4];
    const float* bk  = (const float*)d_in[5];
    const float* wv  = (const float*)d_in[6];
    const float* bv  = (const float*)d_in[7];
    const float* ow  = (const float*)d_in[8];
    const float* ob  = (const float*)d_in[9];
    float* out = (float*)d_out;

    float* G = symaddr<float>(g_G);
    float* T = symaddr<float>(g_T);
    float* E = symaddr<float>(g_E);
    float* P = symaddr<float>(g_P);
    float* R = symaddr<float>(g_R);
    float* s = symaddr<float>(g_s);
    float* u = symaddr<float>(g_u);
    float* v = symaddr<float>(g_v);
    float* w = symaddr<float>(g_w);
    float* z = symaddr<float>(g_z);

    __nv_bfloat16* XtH  = symaddr<__nv_bfloat16>(g_XtH);
    __nv_bfloat16* XtL  = symaddr<__nv_bfloat16>(g_XtL);
    __nv_bfloat16* WqH  = symaddr<__nv_bfloat16>(g_WqH);
    __nv_bfloat16* WqL  = symaddr<__nv_bfloat16>(g_WqL);
    __nv_bfloat16* GH   = symaddr<__nv_bfloat16>(g_GH);
    __nv_bfloat16* GL   = symaddr<__nv_bfloat16>(g_GL);
    __nv_bfloat16* TH   = symaddr<__nv_bfloat16>(g_TH);
    __nv_bfloat16* TL   = symaddr<__nv_bfloat16>(g_TL);
    __nv_bfloat16* WkH  = symaddr<__nv_bfloat16>(g_WkH);
    __nv_bfloat16* WkL  = symaddr<__nv_bfloat16>(g_WkL);
    __nv_bfloat16* WvTH = symaddr<__nv_bfloat16>(g_WvTH);
    __nv_bfloat16* WvTL = symaddr<__nv_bfloat16>(g_WvTL);
    __nv_bfloat16* AtH  = symaddr<__nv_bfloat16>(g_AtH);
    __nv_bfloat16* AtL  = symaddr<__nv_bfloat16>(g_AtL);
    __nv_bfloat16* PH   = symaddr<__nv_bfloat16>(g_PH);
    __nv_bfloat16* PL   = symaddr<__nv_bfloat16>(g_PL);
    __nv_bfloat16* OH   = symaddr<__nv_bfloat16>(g_OH);
    __nv_bfloat16* OL   = symaddr<__nv_bfloat16>(g_OL);
    __nv_bfloat16* RtH  = symaddr<__nv_bfloat16>(g_RtH);
    __nv_bfloat16* RtL  = symaddr<__nv_bfloat16>(g_RtL);
    __nv_bfloat16* XH   = symaddr<__nv_bfloat16>(g_XH);
    __nv_bfloat16* XL   = symaddr<__nv_bfloat16>(g_XL);

    cudaFuncSetAttribute(mma_gemm, cudaFuncAttributeMaxDynamicSharedMemorySize, GEMM_SMEM);

    dim3 tb(32, 8);

    // input/weight conversions (hi/lo separated, coalesced)
    tsplit2_kernel<<<dim3(LO/32, Nn/32, Bb), tb>>>(X, (long)Nn*LO, XtH, XtL, (long)LO*Nn, Nn, LO);
    split2_kernel<<<dim3(512, 1), 256>>>(wq, 0, WqH, WqL, 0, LO*LO/2);
    split2_kernel<<<dim3(4096, 1), 256>>>(wk, 0, WkH, WkL, 0, HI*LO/2);
    tsplit2_kernel<<<dim3(LO/32, LO/32, 1), tb>>>(wv, 0, WvTH, WvTL, 0, LO, LO);
    split2_kernel<<<dim3(8192, 1), 256>>>(ow, 0, OH, OL, 0, HI*HI/2);
    split2_kernel<<<dim3(2048, Bb), 256>>>(X, (long)Nn*LO, XH, XL, (long)Nn*LO, Nn*LO/2);

    // bias correction vectors (exact; zero-valued in this dataset)
    colsum_kernel<<<Bb, LO>>>(X, s);
    rowdot_kernel<<<dim3(LO/8, Bb), 256>>>(wq, s, u, LO, LO, nullptr);
    rowdot_kernel<<<dim3(HI/8, Bb), 256>>>(wk, s, v, HI, LO, nullptr);

    // G_b = Xt Xt^T   [512,512] K=2048
    mma_gemm<<<dim3(LO/128, LO/128, Bb), 256, GEMM_SMEM>>>(
        Nn, XtH, XtL, (long)LO*Nn, XtH, XtL, (long)LO*Nn,
        G, LO, (long)LO*LO, nullptr, 0);
    split2_kernel<<<dim3(512, Bb), 256>>>(G, (long)LO*LO, GH, GL, (long)LO*LO, LO*LO/2);

    // T_b = Wq G_b    (G symmetric => rows of G are K-major columns)
    mma_gemm<<<dim3(LO/128, LO/128, Bb), 256, GEMM_SMEM>>>(
        LO, WqH, WqL, 0, GH, GL, (long)LO*LO,
        T, LO, (long)LO*LO, nullptr, 0);
    split2_kernel<<<dim3(512, Bb), 256>>>(T, (long)LO*LO, TH, TL, (long)LO*LO, LO*LO/2);

    // E_b = T_b Wk^T  [512,4096] K=512
    mma_gemm<<<dim3(HI/128, LO/128, Bb), 256, GEMM_SMEM>>>(
        LO, TH, TL, (long)LO*LO, WkH, WkL, 0,
        E, HI, (long)LO*HI, nullptr, 0);

    // A_b = softmax(e) + softmax(minmaxnorm(e, mask)), in place in E
    attn_kernel<<<dim3(LO, Bb), 256>>>(E, lk, u, bq, v, bk);

    // bias path: w_b = bv^T A_b ; z_b = w_b O^T + o_b
    wvec_kernel<<<dim3(HI/256, Bb), 256>>>(E, bv, w);
    rowdot_kernel<<<dim3(HI/8, Bb), 256>>>(ow, w, z, HI, HI, ob);

    // P_b = Wv^T A_b  (B operand is A^T via transpose-split)
    tsplit2_kernel<<<dim3(HI/32, LO/32, Bb), tb>>>(E, (long)LO*HI, AtH, AtL, (long)HI*LO, LO, HI);
    mma_gemm<<<dim3(HI/128, LO/128, Bb), 256, GEMM_SMEM>>>(
        LO, WvTH, WvTL, 0, AtH, AtL, (long)HI*LO,
        P, HI, (long)LO*HI, nullptr, 0);

    // R_b = P_b O^T   [512,4096] K=4096 (dominant)
    split2_kernel<<<dim3(4096, Bb), 256>>>(P, (long)LO*HI, PH, PL, (long)LO*HI, LO*HI/2);
    mma_gemm<<<dim3(HI/128, LO/128, Bb), 256, GEMM_SMEM>>>(
        HI, PH, PL, (long)LO*HI, OH, OL, 0,
        R, HI, (long)LO*HI, nullptr, 0);

    // out_b = X_b R_b + z_b  [2048,4096] K=512 (B operand is R^T)
    tsplit2_kernel<<<dim3(HI/32, LO/32, Bb), tb>>>(R, (long)LO*HI, RtH, RtL, (long)HI*LO, LO, HI);
    mma_gemm<<<dim3(HI/128, Nn/128, Bb), 256, GEMM_SMEM>>>(
        LO, XH, XL, (long)Nn*LO, RtH, RtL, (long)HI*LO,
        out, HI, (long)Nn*HI, z, HI);

    (void)in_sizes; (void)n_in; (void)out_size;
}